// round 9
// baseline (speedup 1.0000x reference)
#include <cuda_runtime.h>
#include <cuda_bf16.h>
#include <math.h>
#include <stdint.h>

#define N_NODES 50000
#define N_EDGES 800000
#define DIM     64
#define N_LAYERS 5

#define SCAN_BLK  512
#define SCAN_NBLK ((N_NODES + SCAN_BLK - 1) / SCAN_BLK)   // 98

// Scratch (no allocations allowed -> __device__ globals)
__device__ float g_agg[N_NODES * DIM];
__device__ float g_h[N_NODES * DIM];
__device__ float g_pooled[N_LAYERS * DIM];
__device__ int   g_deg[N_NODES];
__device__ int   g_off[N_NODES + 1];
__device__ int   g_csr[N_EDGES];
__device__ int   g_bsum[SCAN_NBLK];

// ---------------------------------------------------------------------------
// CSR build (unchanged — known good)
// ---------------------------------------------------------------------------
__global__ void k_zero()
{
    int i = blockIdx.x * blockDim.x + threadIdx.x;
    if (i < N_NODES) g_deg[i] = 0;
    if (i < N_LAYERS * DIM) g_pooled[i] = 0.0f;
}

__global__ void k_count(const int* __restrict__ dst)
{
    int e = blockIdx.x * blockDim.x + threadIdx.x;
    if (e < N_EDGES)
        atomicAdd(&g_deg[dst[e]], 1);
}

__global__ void k_scan_a()
{
    __shared__ int sh[SCAN_BLK];
    int tid = threadIdx.x;
    int i = blockIdx.x * SCAN_BLK + tid;
    sh[tid] = (i < N_NODES) ? g_deg[i] : 0;
    __syncthreads();
    for (int o = SCAN_BLK / 2; o > 0; o >>= 1) {
        if (tid < o) sh[tid] += sh[tid + o];
        __syncthreads();
    }
    if (tid == 0) g_bsum[blockIdx.x] = sh[0];
}

__global__ void k_scan_c()
{
    __shared__ int sh[SCAN_BLK];
    __shared__ int sh2[SCAN_BLK];
    int tid = threadIdx.x;

    sh2[tid] = (tid < blockIdx.x) ? g_bsum[tid] : 0;
    __syncthreads();
    for (int o = SCAN_BLK / 2; o > 0; o >>= 1) {
        if (tid < o) sh2[tid] += sh2[tid + o];
        __syncthreads();
    }
    int boff = sh2[0];

    int i = blockIdx.x * SCAN_BLK + tid;
    int v = (i < N_NODES) ? g_deg[i] : 0;
    sh[tid] = v;
    __syncthreads();
    for (int o = 1; o < SCAN_BLK; o <<= 1) {
        int t = (tid >= o) ? sh[tid - o] : 0;
        __syncthreads();
        sh[tid] += t;
        __syncthreads();
    }
    if (i < N_NODES) {
        g_off[i] = boff + (sh[tid] - v);
        g_deg[i] = 0;
    }
    if (blockIdx.x == 0 && tid == 0) g_off[N_NODES] = N_EDGES;
}

__global__ void k_fill(const int* __restrict__ src, const int* __restrict__ dst)
{
    int e = blockIdx.x * blockDim.x + threadIdx.x;
    if (e < N_EDGES) {
        int d = dst[e];
        int p = atomicAdd(&g_deg[d], 1);
        g_csr[g_off[d] + p] = src[e];
    }
}

// ---------------------------------------------------------------------------
// Gather: agg[v] = h[v] + sum_{u in N(v)} h[u]  (unchanged)
// ---------------------------------------------------------------------------
__global__ void k_gather(const float4* __restrict__ x, int use_x)
{
    int idx = blockIdx.x * blockDim.x + threadIdx.x;
    if (idx >= N_NODES * 16) return;
    int v = idx >> 4;
    int c = idx & 15;

    const float4* hsrc = use_x ? x : reinterpret_cast<const float4*>(g_h);

    float4 acc = __ldg(&hsrc[v * 16 + c]);
    float4 s1 = make_float4(0.f, 0.f, 0.f, 0.f);
    float4 s2 = make_float4(0.f, 0.f, 0.f, 0.f);
    float4 s3 = make_float4(0.f, 0.f, 0.f, 0.f);

    int j = g_off[v];
    int end = g_off[v + 1];

    for (; j + 4 <= end; j += 4) {
        int u0 = __ldg(&g_csr[j]);
        int u1 = __ldg(&g_csr[j + 1]);
        int u2 = __ldg(&g_csr[j + 2]);
        int u3 = __ldg(&g_csr[j + 3]);
        float4 a = __ldg(&hsrc[u0 * 16 + c]);
        float4 b = __ldg(&hsrc[u1 * 16 + c]);
        float4 d = __ldg(&hsrc[u2 * 16 + c]);
        float4 e = __ldg(&hsrc[u3 * 16 + c]);
        acc.x += a.x; acc.y += a.y; acc.z += a.z; acc.w += a.w;
        s1.x += b.x;  s1.y += b.y;  s1.z += b.z;  s1.w += b.w;
        s2.x += d.x;  s2.y += d.y;  s2.z += d.z;  s2.w += d.w;
        s3.x += e.x;  s3.y += e.y;  s3.z += e.z;  s3.w += e.w;
    }
    for (; j < end; j++) {
        float4 a = __ldg(&hsrc[__ldg(&g_csr[j]) * 16 + c]);
        acc.x += a.x; acc.y += a.y; acc.z += a.z; acc.w += a.w;
    }
    acc.x += s1.x + s2.x + s3.x;
    acc.y += s1.y + s2.y + s3.y;
    acc.z += s1.z + s2.z + s3.z;
    acc.w += s1.w + s2.w + s3.w;

    reinterpret_cast<float4*>(g_agg)[v * 16 + c] = acc;
}

// ---------------------------------------------------------------------------
// HMMA MLP (mma.sync bf16, 3-term split for ~fp32 accuracy).
// CTA = 128 nodes, 256 threads = 8 warps; warp w owns rows [16w, 16w+16).
// A (acts) and B (W^T) in XOR-swizzled smem (128B rows, chunk ^= row&7).
// ---------------------------------------------------------------------------
#define TILE_M 128
#define MLP_GRID ((N_NODES + TILE_M - 1) / TILE_M)   // 391

struct __align__(16) TcSmem {
    __nv_bfloat16 a_hi[TILE_M * 64];   // 16384 B
    __nv_bfloat16 a_lo[TILE_M * 64];   // 16384 B
    __nv_bfloat16 b_hi[64 * 64];       //  8192 B
    __nv_bfloat16 b_lo[64 * 64];       //  8192 B
};                                      // 49152 B = 48 KB exactly

__device__ __forceinline__ uint32_t smem_u32(const void* p)
{
    uint32_t a;
    asm("{ .reg .u64 t; cvta.to.shared.u64 t, %1; cvt.u32.u64 %0, t; }"
        : "=r"(a) : "l"(p));
    return a;
}

__device__ __forceinline__ void ldsm4(uint32_t* r, uint32_t addr)
{
    asm volatile("ldmatrix.sync.aligned.m8n8.x4.shared.b16 {%0,%1,%2,%3}, [%4];"
                 : "=r"(r[0]), "=r"(r[1]), "=r"(r[2]), "=r"(r[3]) : "r"(addr));
}
__device__ __forceinline__ void ldsm2(uint32_t* r, uint32_t addr)
{
    asm volatile("ldmatrix.sync.aligned.m8n8.x2.shared.b16 {%0,%1}, [%2];"
                 : "=r"(r[0]), "=r"(r[1]) : "r"(addr));
}
__device__ __forceinline__ void mma16816(float* d, const uint32_t* a, const uint32_t* b)
{
    asm volatile("mma.sync.aligned.m16n8k16.row.col.f32.bf16.bf16.f32 "
                 "{%0,%1,%2,%3}, {%4,%5,%6,%7}, {%8,%9}, {%0,%1,%2,%3};"
                 : "+f"(d[0]), "+f"(d[1]), "+f"(d[2]), "+f"(d[3])
                 : "r"(a[0]), "r"(a[1]), "r"(a[2]), "r"(a[3]),
                   "r"(b[0]), "r"(b[1]));
}

__global__ __launch_bounds__(256) void k_mlp_hmma(const float* __restrict__ W,
                                                  int layer)
{
    __shared__ TcSmem sm;

    int tid  = threadIdx.x;
    int lane = tid & 31;
    int w    = tid >> 5;            // warp 0..7
    int m0   = w * 16;
    int blockBase = blockIdx.x * TILE_M;

    char* a_hi_c = reinterpret_cast<char*>(sm.a_hi);
    char* a_lo_c = reinterpret_cast<char*>(sm.a_lo);
    char* b_hi_c = reinterpret_cast<char*>(sm.b_hi);
    char* b_lo_c = reinterpret_cast<char*>(sm.b_lo);

    // ---- initial A: split gather output into bf16 hi/lo, swizzled ----
    {
        int row  = tid >> 1;
        int half = tid & 1;
        int node = blockBase + row;
        float v[32];
        if (node < N_NODES) {
            const float4* srcp = reinterpret_cast<const float4*>(g_agg + node * DIM + half * 32);
#pragma unroll
            for (int i = 0; i < 8; i++) {
                float4 t = srcp[i];
                v[4*i] = t.x; v[4*i+1] = t.y; v[4*i+2] = t.z; v[4*i+3] = t.w;
            }
        } else {
#pragma unroll
            for (int i = 0; i < 32; i++) v[i] = 0.f;
        }
#pragma unroll
        for (int p = 0; p < 16; p++) {
            int pp = half * 16 + p;
            float x0 = v[2*p], x1 = v[2*p+1];
            __nv_bfloat16 h0 = __float2bfloat16(x0), h1 = __float2bfloat16(x1);
            float l0 = x0 - __bfloat162float(h0), l1 = x1 - __bfloat162float(h1);
            uint32_t hi = (uint32_t)__bfloat16_as_ushort(h0) |
                          ((uint32_t)__bfloat16_as_ushort(h1) << 16);
            uint32_t lo = (uint32_t)__bfloat16_as_ushort(__float2bfloat16(l0)) |
                          ((uint32_t)__bfloat16_as_ushort(__float2bfloat16(l1)) << 16);
            uint32_t off = (uint32_t)row * 128 + ((((uint32_t)pp >> 2) ^ (row & 7)) << 4)
                         + (pp & 3) * 4;
            *reinterpret_cast<uint32_t*>(a_hi_c + off) = hi;
            *reinterpret_cast<uint32_t*>(a_lo_c + off) = lo;
        }
    }

    uint32_t a_hi_base = smem_u32(sm.a_hi);
    uint32_t a_lo_base = smem_u32(sm.a_lo);
    uint32_t b_hi_base = smem_u32(sm.b_hi);
    uint32_t b_lo_base = smem_u32(sm.b_lo);

    int r0 = m0 + (lane >> 2);      // accum row 0 for this thread
    int r1 = r0 + 8;                // accum row 1

    for (int s = 0; s < 3; s++) {
        // ---- load stage weights, split, transpose to B[n][k] swizzled ----
        {
            const float4* Wst = reinterpret_cast<const float4*>(
                W + ((size_t)layer * 3 + s) * DIM * DIM);
#pragma unroll
            for (int q = 0; q < 4; q++) {
                float4 t = Wst[tid * 4 + q];
                float e[4] = {t.x, t.y, t.z, t.w};
#pragma unroll
                for (int j = 0; j < 4; j++) {
                    int idx = tid * 16 + q * 4 + j;
                    int k = idx >> 6, n = idx & 63;
                    __nv_bfloat16 wh = __float2bfloat16(e[j]);
                    float wlf = e[j] - __bfloat162float(wh);
                    uint32_t off = (uint32_t)n * 128 + ((((uint32_t)k >> 3) ^ (n & 7)) << 4)
                                 + (k & 7) * 2;
                    *reinterpret_cast<__nv_bfloat16*>(b_hi_c + off) = wh;
                    *reinterpret_cast<__nv_bfloat16*>(b_lo_c + off) = __float2bfloat16(wlf);
                }
            }
        }
        __syncthreads();

        // ---- MMA: acc[nt] over 4 k-steps, 3 split terms ----
        float acc[8][4];
#pragma unroll
        for (int nt = 0; nt < 8; nt++)
#pragma unroll
            for (int j = 0; j < 4; j++) acc[nt][j] = 0.f;

#pragma unroll
        for (int kk = 0; kk < 4; kk++) {
            int arow = m0 + (lane & 15);
            uint32_t achunk = (uint32_t)(kk * 2 + (lane >> 4));
            uint32_t aoff = (uint32_t)arow * 128 + ((achunk ^ (arow & 7)) << 4);
            uint32_t ah[4], al[4];
            ldsm4(ah, a_hi_base + aoff);
            ldsm4(al, a_lo_base + aoff);

            int brow_l = lane & 7;
            uint32_t bchunk = (uint32_t)(kk * 2 + ((lane >> 3) & 1));
#pragma unroll
            for (int nt = 0; nt < 8; nt++) {
                int brow = nt * 8 + brow_l;
                uint32_t boff = (uint32_t)brow * 128 + ((bchunk ^ (brow & 7)) << 4);
                uint32_t bh[2], bl[2];
                ldsm2(bh, b_hi_base + boff);
                ldsm2(bl, b_lo_base + boff);
                mma16816(acc[nt], ah, bh);
                mma16816(acc[nt], al, bh);
                mma16816(acc[nt], ah, bl);
            }
        }
        __syncthreads();   // all warps done reading A/B before rewrite

        if (s < 2) {
            // ---- epilogue: ReLU, re-split into A hi/lo for next stage ----
#pragma unroll
            for (int nt = 0; nt < 8; nt++) {
                float v00 = fmaxf(acc[nt][0], 0.f);
                float v01 = fmaxf(acc[nt][1], 0.f);
                float v10 = fmaxf(acc[nt][2], 0.f);
                float v11 = fmaxf(acc[nt][3], 0.f);
                int p = nt * 4 + (lane & 3);   // bf16-pair index in row
                uint32_t sw = (uint32_t)(((p >> 2) ^ (r0 & 7)) << 4) + (p & 3) * 4;
                uint32_t sw1 = (uint32_t)(((p >> 2) ^ (r1 & 7)) << 4) + (p & 3) * 4;

                __nv_bfloat16 h0 = __float2bfloat16(v00), h1 = __float2bfloat16(v01);
                float l0 = v00 - __bfloat162float(h0), l1 = v01 - __bfloat162float(h1);
                *reinterpret_cast<uint32_t*>(a_hi_c + (uint32_t)r0 * 128 + sw) =
                    (uint32_t)__bfloat16_as_ushort(h0) |
                    ((uint32_t)__bfloat16_as_ushort(h1) << 16);
                *reinterpret_cast<uint32_t*>(a_lo_c + (uint32_t)r0 * 128 + sw) =
                    (uint32_t)__bfloat16_as_ushort(__float2bfloat16(l0)) |
                    ((uint32_t)__bfloat16_as_ushort(__float2bfloat16(l1)) << 16);

                __nv_bfloat16 g0 = __float2bfloat16(v10), g1 = __float2bfloat16(v11);
                float m0f = v10 - __bfloat162float(g0), m1f = v11 - __bfloat162float(g1);
                *reinterpret_cast<uint32_t*>(a_hi_c + (uint32_t)r1 * 128 + sw1) =
                    (uint32_t)__bfloat16_as_ushort(g0) |
                    ((uint32_t)__bfloat16_as_ushort(g1) << 16);
                *reinterpret_cast<uint32_t*>(a_lo_c + (uint32_t)r1 * 128 + sw1) =
                    (uint32_t)__bfloat16_as_ushort(__float2bfloat16(m0f)) |
                    ((uint32_t)__bfloat16_as_ushort(__float2bfloat16(m1f)) << 16);
            }
        } else {
            // ---- final epilogue: h write + pooled sum (pool overlays b_hi) ----
            float* pool = reinterpret_cast<float*>(sm.b_hi);
            if (tid < DIM) pool[tid] = 0.f;
            __syncthreads();

            int node0 = blockBase + r0;
            int node1 = blockBase + r1;
#pragma unroll
            for (int nt = 0; nt < 8; nt++) {
                float v00 = fmaxf(acc[nt][0], 0.f);
                float v01 = fmaxf(acc[nt][1], 0.f);
                float v10 = fmaxf(acc[nt][2], 0.f);
                float v11 = fmaxf(acc[nt][3], 0.f);
                int c0 = nt * 8 + (lane & 3) * 2;
                if (node0 < N_NODES)
                    *reinterpret_cast<float2*>(g_h + node0 * DIM + c0) =
                        make_float2(v00, v01);
                if (node1 < N_NODES)
                    *reinterpret_cast<float2*>(g_h + node1 * DIM + c0) =
                        make_float2(v10, v11);
                atomicAdd(&pool[c0],     v00 + v10);
                atomicAdd(&pool[c0 + 1], v01 + v11);
            }
            __syncthreads();
            if (tid < DIM)
                atomicAdd(&g_pooled[layer * DIM + tid], pool[tid]);
        }
    }
}

// ---------------------------------------------------------------------------
// Final: out = sigmoid( sum_l dot(pooled_l / N, Wl_l) )
// ---------------------------------------------------------------------------
__global__ void k_final(const float* __restrict__ Wl, float* __restrict__ out)
{
    __shared__ float red[128];
    int tid = threadIdx.x;
    float s = 0.0f;
    for (int i = tid; i < N_LAYERS * DIM; i += 128)
        s += g_pooled[i] * Wl[i];
    red[tid] = s;
    __syncthreads();
    for (int o = 64; o > 0; o >>= 1) {
        if (tid < o) red[tid] += red[tid + o];
        __syncthreads();
    }
    if (tid == 0) {
        float v = red[0] / (float)N_NODES;
        out[0] = 1.0f / (1.0f + expf(-v));
    }
}

// ---------------------------------------------------------------------------
// Launch
// ---------------------------------------------------------------------------
extern "C" void kernel_launch(void* const* d_in, const int* in_sizes, int n_in,
                              void* d_out, int out_size)
{
    const float* x   = (const float*)d_in[0];
    const float* W   = (const float*)d_in[1];
    const float* Wl  = (const float*)d_in[2];
    const int*   src = (const int*)d_in[3];
    const int*   dst = (const int*)d_in[4];
    float*       out = (float*)d_out;

    (void)in_sizes; (void)n_in; (void)out_size;

    // CSR build
    k_zero<<<(N_NODES + 255) / 256, 256>>>();
    k_count<<<(N_EDGES + 255) / 256, 256>>>(dst);
    k_scan_a<<<SCAN_NBLK, SCAN_BLK>>>();
    k_scan_c<<<SCAN_NBLK, SCAN_BLK>>>();
    k_fill<<<(N_EDGES + 255) / 256, 256>>>(src, dst);

    int gather_blocks = (N_NODES * 16 + 255) / 256;

    for (int l = 0; l < N_LAYERS; l++) {
        k_gather<<<gather_blocks, 256>>>((const float4*)x, l == 0 ? 1 : 0);
        k_mlp_hmma<<<MLP_GRID, 256>>>(W, l);
    }
    k_final<<<1, 128>>>(Wl, out);
}

// round 10
// speedup vs baseline: 1.0348x; 1.0348x over previous
#include <cuda_runtime.h>
#include <math.h>
#include <stdint.h>

#define N_NODES 50000
#define N_EDGES 800000
#define DIM     64
#define N_LAYERS 5

#define SCAN_BLK  512
#define SCAN_NBLK ((N_NODES + SCAN_BLK - 1) / SCAN_BLK)   // 98

#define FLAG_AGG (1u << 30)
#define FLAG_INC (2u << 30)
#define VAL_MASK (FLAG_AGG - 1u)

// Scratch (no allocations allowed -> __device__ globals).
// Zero-init state contract across graph replays:
//   g_deg   : zeroed by k_fill (for next replay); .bss zero on first run
//   g_sstate: zeroed by k_fill (for next replay); .bss zero on first run
//   g_cur   : zeroed by k_scan (same replay, before k_fill uses it)
//   g_pooled: zeroed by k_final after consumption; .bss zero on first run
__device__ float    g_agg[N_NODES * DIM];
__device__ float    g_h[N_NODES * DIM];
__device__ float    g_pooled[N_LAYERS * DIM];
__device__ int      g_deg[N_NODES];
__device__ int      g_cur[N_NODES];
__device__ int      g_off[N_NODES + 1];
__device__ int      g_csr[N_EDGES];
__device__ unsigned g_sstate[SCAN_NBLK];

// ---------------------------------------------------------------------------
// CSR step 1: histogram of dst  (g_deg arrives zeroed)
// ---------------------------------------------------------------------------
__global__ void k_count(const int* __restrict__ dst)
{
    int e = blockIdx.x * blockDim.x + threadIdx.x;
    if (e < N_EDGES)
        atomicAdd(&g_deg[dst[e]], 1);
}

// ---------------------------------------------------------------------------
// CSR step 2: single-pass exclusive scan (decoupled lookback, warp-parallel).
// Packed state word: flag[31:30] | value[29:0]  (values <= 800000 < 2^30).
// All 98 blocks are co-resident (98 < 148 SMs) -> no deadlock.
// Also zeroes g_cur for k_fill.
// ---------------------------------------------------------------------------
__global__ void k_scan()
{
    __shared__ int sh[SCAN_BLK];
    __shared__ int s_prefix;
    int tid = threadIdx.x;
    int b   = blockIdx.x;
    int i   = b * SCAN_BLK + tid;
    int v   = (i < N_NODES) ? g_deg[i] : 0;

    sh[tid] = v;
    __syncthreads();
    for (int o = 1; o < SCAN_BLK; o <<= 1) {
        int t = (tid >= o) ? sh[tid - o] : 0;
        __syncthreads();
        sh[tid] += t;
        __syncthreads();
    }
    int total = sh[SCAN_BLK - 1];

    if (tid < 32) {
        int lane = tid;
        if (lane == 0) {
            unsigned pub = (b == 0) ? (FLAG_INC | (unsigned)total)
                                    : (FLAG_AGG | (unsigned)total);
            atomicExch(&g_sstate[b], pub);
        }
        __syncwarp();

        int run = 0;
        if (b > 0) {
            int j = b - 1;
            while (true) {
                int idx = j - lane;
                bool have = (idx >= 0);
                unsigned s = 0;
                if (have) {
                    do { s = atomicAdd(&g_sstate[idx], 0u); } while (s < FLAG_AGG);
                }
                unsigned incmask = __ballot_sync(0xffffffffu, have && (s >= FLAG_INC));
                int firstinc = incmask ? (__ffs(incmask) - 1) : 32;
                unsigned contrib = (have && lane <= firstinc) ? (s & VAL_MASK) : 0u;
                for (int o = 16; o > 0; o >>= 1)
                    contrib += __shfl_down_sync(0xffffffffu, contrib, o);
                contrib = __shfl_sync(0xffffffffu, contrib, 0);
                run += (int)contrib;
                if (incmask) break;
                j -= 32;
            }
            if (lane == 0)
                atomicExch(&g_sstate[b], FLAG_INC | (unsigned)(run + total));
        }
        if (lane == 0) s_prefix = run;
    }
    __syncthreads();

    if (i < N_NODES) {
        g_off[i] = s_prefix + (sh[tid] - v);
        g_cur[i] = 0;
    }
    if (b == 0 && tid == 0) g_off[N_NODES] = N_EDGES;
}

// ---------------------------------------------------------------------------
// CSR step 3: bucket-fill src by dst (cursor = g_cur).
// Also re-zeroes g_deg and g_sstate for the NEXT graph replay.
// ---------------------------------------------------------------------------
__global__ void k_fill(const int* __restrict__ src, const int* __restrict__ dst)
{
    int e = blockIdx.x * blockDim.x + threadIdx.x;
    if (e < N_EDGES) {
        int d = dst[e];
        int p = atomicAdd(&g_cur[d], 1);
        g_csr[g_off[d] + p] = src[e];
    }
    if (e < N_NODES) g_deg[e] = 0;
    if (e < SCAN_NBLK) g_sstate[e] = 0;
}

// ---------------------------------------------------------------------------
// Gather: agg[v] = h[v] + sum_{u in N(v)} h[u]  (unchanged; launch idx 3
// so ncu's deterministic capture lands on it)
// ---------------------------------------------------------------------------
__global__ void k_gather(const float4* __restrict__ x, int use_x)
{
    int idx = blockIdx.x * blockDim.x + threadIdx.x;
    if (idx >= N_NODES * 16) return;
    int v = idx >> 4;
    int c = idx & 15;

    const float4* hsrc = use_x ? x : reinterpret_cast<const float4*>(g_h);

    float4 acc = __ldg(&hsrc[v * 16 + c]);
    float4 s1 = make_float4(0.f, 0.f, 0.f, 0.f);
    float4 s2 = make_float4(0.f, 0.f, 0.f, 0.f);
    float4 s3 = make_float4(0.f, 0.f, 0.f, 0.f);

    int j = g_off[v];
    int end = g_off[v + 1];

    for (; j + 4 <= end; j += 4) {
        int u0 = __ldg(&g_csr[j]);
        int u1 = __ldg(&g_csr[j + 1]);
        int u2 = __ldg(&g_csr[j + 2]);
        int u3 = __ldg(&g_csr[j + 3]);
        float4 a = __ldg(&hsrc[u0 * 16 + c]);
        float4 b = __ldg(&hsrc[u1 * 16 + c]);
        float4 d = __ldg(&hsrc[u2 * 16 + c]);
        float4 e = __ldg(&hsrc[u3 * 16 + c]);
        acc.x += a.x; acc.y += a.y; acc.z += a.z; acc.w += a.w;
        s1.x += b.x;  s1.y += b.y;  s1.z += b.z;  s1.w += b.w;
        s2.x += d.x;  s2.y += d.y;  s2.z += d.z;  s2.w += d.w;
        s3.x += e.x;  s3.y += e.y;  s3.z += e.z;  s3.w += e.w;
    }
    for (; j < end; j++) {
        float4 a = __ldg(&hsrc[__ldg(&g_csr[j]) * 16 + c]);
        acc.x += a.x; acc.y += a.y; acc.z += a.z; acc.w += a.w;
    }
    acc.x += s1.x + s2.x + s3.x;
    acc.y += s1.y + s2.y + s3.y;
    acc.z += s1.z + s2.z + s3.z;
    acc.w += s1.w + s2.w + s3.w;

    reinterpret_cast<float4*>(g_agg)[v * 16 + c] = acc;
}

// ---------------------------------------------------------------------------
// MLP (R7 FFMA2 version — best measured). 256 thr = 4 groups of 64, NB=16.
// ---------------------------------------------------------------------------
#define NB  16
#define NBP 20
#define GROUPS 4
#define NODES_PER_BLOCK (GROUPS * NB)   // 64

__global__ __launch_bounds__(256) void k_mlp(const float* __restrict__ W, int layer)
{
    __shared__ __align__(16) float Ws[DIM * DIM];
    __shared__ __align__(16) float bufA[GROUPS * DIM * NBP];
    __shared__ __align__(16) float bufB[GROUPS * DIM * NBP];
    __shared__ float poolsh[DIM];

    int tid = threadIdx.x;
    int g   = tid >> 6;
    int t   = tid & 63;
    int base = blockIdx.x * NODES_PER_BLOCK + g * NB;

#pragma unroll
    for (int n = 0; n < NB; n++) {
        int node = base + n;
        bufA[(g * DIM + t) * NBP + n] = (node < N_NODES) ? g_agg[node * DIM + t] : 0.0f;
    }
    if (tid < DIM) poolsh[tid] = 0.0f;

    const float* Wbase = W + (size_t)layer * 3 * DIM * DIM;

    float* inb  = bufA;
    float* outb = bufB;
    float psum = 0.0f;

    for (int s = 0; s < 3; s++) {
        __syncthreads();
        const float4* Wst = reinterpret_cast<const float4*>(Wbase + s * DIM * DIM);
        float4* Wsv = reinterpret_cast<float4*>(Ws);
#pragma unroll
        for (int i = 0; i < DIM * DIM / 4 / 256; i++)
            Wsv[i * 256 + tid] = Wst[i * 256 + tid];
        __syncthreads();

        unsigned long long acc0 = 0ull, acc1 = 0ull, acc2 = 0ull, acc3 = 0ull;
        unsigned long long acc4 = 0ull, acc5 = 0ull, acc6 = 0ull, acc7 = 0ull;
        const ulonglong2* in2 =
            reinterpret_cast<const ulonglong2*>(inb + g * DIM * NBP);

#pragma unroll 4
        for (int k = 0; k < DIM; k++) {
            unsigned int wb = __float_as_uint(Ws[k * DIM + t]);
            unsigned long long wp;
            asm("mov.b64 %0, {%1, %1};" : "=l"(wp) : "r"(wb));
            ulonglong2 q0 = in2[k * 5 + 0];
            ulonglong2 q1 = in2[k * 5 + 1];
            ulonglong2 q2 = in2[k * 5 + 2];
            ulonglong2 q3 = in2[k * 5 + 3];
            asm("fma.rn.f32x2 %0, %1, %2, %0;" : "+l"(acc0) : "l"(q0.x), "l"(wp));
            asm("fma.rn.f32x2 %0, %1, %2, %0;" : "+l"(acc1) : "l"(q0.y), "l"(wp));
            asm("fma.rn.f32x2 %0, %1, %2, %0;" : "+l"(acc2) : "l"(q1.x), "l"(wp));
            asm("fma.rn.f32x2 %0, %1, %2, %0;" : "+l"(acc3) : "l"(q1.y), "l"(wp));
            asm("fma.rn.f32x2 %0, %1, %2, %0;" : "+l"(acc4) : "l"(q2.x), "l"(wp));
            asm("fma.rn.f32x2 %0, %1, %2, %0;" : "+l"(acc5) : "l"(q2.y), "l"(wp));
            asm("fma.rn.f32x2 %0, %1, %2, %0;" : "+l"(acc6) : "l"(q3.x), "l"(wp));
            asm("fma.rn.f32x2 %0, %1, %2, %0;" : "+l"(acc7) : "l"(q3.y), "l"(wp));
        }

        float o[NB];
        {
            float2 a;
            a = *reinterpret_cast<float2*>(&acc0); o[0]  = fmaxf(a.x, 0.f); o[1]  = fmaxf(a.y, 0.f);
            a = *reinterpret_cast<float2*>(&acc1); o[2]  = fmaxf(a.x, 0.f); o[3]  = fmaxf(a.y, 0.f);
            a = *reinterpret_cast<float2*>(&acc2); o[4]  = fmaxf(a.x, 0.f); o[5]  = fmaxf(a.y, 0.f);
            a = *reinterpret_cast<float2*>(&acc3); o[6]  = fmaxf(a.x, 0.f); o[7]  = fmaxf(a.y, 0.f);
            a = *reinterpret_cast<float2*>(&acc4); o[8]  = fmaxf(a.x, 0.f); o[9]  = fmaxf(a.y, 0.f);
            a = *reinterpret_cast<float2*>(&acc5); o[10] = fmaxf(a.x, 0.f); o[11] = fmaxf(a.y, 0.f);
            a = *reinterpret_cast<float2*>(&acc6); o[12] = fmaxf(a.x, 0.f); o[13] = fmaxf(a.y, 0.f);
            a = *reinterpret_cast<float2*>(&acc7); o[14] = fmaxf(a.x, 0.f); o[15] = fmaxf(a.y, 0.f);
        }

        float* ob = outb + (g * DIM + t) * NBP;
        reinterpret_cast<float4*>(ob)[0] = make_float4(o[0],  o[1],  o[2],  o[3]);
        reinterpret_cast<float4*>(ob)[1] = make_float4(o[4],  o[5],  o[6],  o[7]);
        reinterpret_cast<float4*>(ob)[2] = make_float4(o[8],  o[9],  o[10], o[11]);
        reinterpret_cast<float4*>(ob)[3] = make_float4(o[12], o[13], o[14], o[15]);

        if (s == 2) {
            float ps = 0.0f;
#pragma unroll
            for (int n = 0; n < NB; n++) {
                int node = base + n;
                if (node < N_NODES) {
                    g_h[node * DIM + t] = o[n];
                    ps += o[n];
                }
            }
            psum = ps;
        }
        float* tmp = inb; inb = outb; outb = tmp;
    }

    __syncthreads();
    atomicAdd(&poolsh[t], psum);
    __syncthreads();
    if (tid < DIM)
        atomicAdd(&g_pooled[layer * DIM + tid], poolsh[tid]);
}

// ---------------------------------------------------------------------------
// Final: out = sigmoid( sum_l dot(pooled_l / N, Wl_l) ); re-zero g_pooled
// ---------------------------------------------------------------------------
__global__ void k_final(const float* __restrict__ Wl, float* __restrict__ out)
{
    __shared__ float red[128];
    int tid = threadIdx.x;
    float s = 0.0f;
    for (int i = tid; i < N_LAYERS * DIM; i += 128)
        s += g_pooled[i] * Wl[i];
    red[tid] = s;
    __syncthreads();
    // all reads of g_pooled are complete past this barrier -> safe to re-zero
    for (int i = tid; i < N_LAYERS * DIM; i += 128)
        g_pooled[i] = 0.0f;
    for (int o = 64; o > 0; o >>= 1) {
        if (tid < o) red[tid] += red[tid + o];
        __syncthreads();
    }
    if (tid == 0) {
        float v = red[0] / (float)N_NODES;
        out[0] = 1.0f / (1.0f + expf(-v));
    }
}

// ---------------------------------------------------------------------------
// Launch (gather is launch idx 3 -> ncu capture target)
// ---------------------------------------------------------------------------
extern "C" void kernel_launch(void* const* d_in, const int* in_sizes, int n_in,
                              void* d_out, int out_size)
{
    const float* x   = (const float*)d_in[0];
    const float* W   = (const float*)d_in[1];
    const float* Wl  = (const float*)d_in[2];
    const int*   src = (const int*)d_in[3];
    const int*   dst = (const int*)d_in[4];
    float*       out = (float*)d_out;

    (void)in_sizes; (void)n_in; (void)out_size;

    k_count<<<(N_EDGES + 255) / 256, 256>>>(dst);          // idx 0
    k_scan<<<SCAN_NBLK, SCAN_BLK>>>();                     // idx 1
    k_fill<<<(N_EDGES + 255) / 256, 256>>>(src, dst);      // idx 2

    int gather_blocks = (N_NODES * 16 + 255) / 256;
    int mlp_blocks    = (N_NODES + NODES_PER_BLOCK - 1) / NODES_PER_BLOCK;

    for (int l = 0; l < N_LAYERS; l++) {
        k_gather<<<gather_blocks, 256>>>((const float4*)x, l == 0 ? 1 : 0);  // idx 3 first
        k_mlp<<<mlp_blocks, 256>>>(W, l);
    }
    k_final<<<1, 128>>>(Wl, out);
}

// round 11
// speedup vs baseline: 1.0535x; 1.0180x over previous
#include <cuda_runtime.h>
#include <math.h>
#include <stdint.h>

#define N_NODES 50000
#define N_EDGES 800000
#define DIM     64
#define N_LAYERS 5

#define SCAN_BLK  512
#define SCAN_NBLK ((N_NODES + SCAN_BLK - 1) / SCAN_BLK)   // 98

#define FLAG_AGG (1u << 30)
#define FLAG_INC (2u << 30)
#define VAL_MASK (FLAG_AGG - 1u)

// Scratch (no allocations -> __device__ globals).
// Replay contract: g_deg/g_sstate re-zeroed by k_fill; g_cur by k_scan;
// g_pooled by k_final. .bss zero on first run.
__device__ float    g_h[N_NODES * DIM];
__device__ float    g_pooled[N_LAYERS * DIM];
__device__ int      g_deg[N_NODES];
__device__ int      g_cur[N_NODES];
__device__ int      g_off[N_NODES + 1];
__device__ int      g_csr[N_EDGES];
__device__ unsigned g_sstate[SCAN_NBLK];

// ---------------------------------------------------------------------------
// CSR step 1: histogram of dst
// ---------------------------------------------------------------------------
__global__ void k_count(const int* __restrict__ dst)
{
    int e = blockIdx.x * blockDim.x + threadIdx.x;
    if (e < N_EDGES)
        atomicAdd(&g_deg[dst[e]], 1);
}

// ---------------------------------------------------------------------------
// CSR step 2: single-pass exclusive scan (decoupled lookback). Zeroes g_cur.
// ---------------------------------------------------------------------------
__global__ void k_scan()
{
    __shared__ int sh[SCAN_BLK];
    __shared__ int s_prefix;
    int tid = threadIdx.x;
    int b   = blockIdx.x;
    int i   = b * SCAN_BLK + tid;
    int v   = (i < N_NODES) ? g_deg[i] : 0;

    sh[tid] = v;
    __syncthreads();
    for (int o = 1; o < SCAN_BLK; o <<= 1) {
        int t = (tid >= o) ? sh[tid - o] : 0;
        __syncthreads();
        sh[tid] += t;
        __syncthreads();
    }
    int total = sh[SCAN_BLK - 1];

    if (tid < 32) {
        int lane = tid;
        if (lane == 0) {
            unsigned pub = (b == 0) ? (FLAG_INC | (unsigned)total)
                                    : (FLAG_AGG | (unsigned)total);
            atomicExch(&g_sstate[b], pub);
        }
        __syncwarp();

        int run = 0;
        if (b > 0) {
            int j = b - 1;
            while (true) {
                int idx = j - lane;
                bool have = (idx >= 0);
                unsigned s = 0;
                if (have) {
                    do { s = atomicAdd(&g_sstate[idx], 0u); } while (s < FLAG_AGG);
                }
                unsigned incmask = __ballot_sync(0xffffffffu, have && (s >= FLAG_INC));
                int firstinc = incmask ? (__ffs(incmask) - 1) : 32;
                unsigned contrib = (have && lane <= firstinc) ? (s & VAL_MASK) : 0u;
                for (int o = 16; o > 0; o >>= 1)
                    contrib += __shfl_down_sync(0xffffffffu, contrib, o);
                contrib = __shfl_sync(0xffffffffu, contrib, 0);
                run += (int)contrib;
                if (incmask) break;
                j -= 32;
            }
            if (lane == 0)
                atomicExch(&g_sstate[b], FLAG_INC | (unsigned)(run + total));
        }
        if (lane == 0) s_prefix = run;
    }
    __syncthreads();

    if (i < N_NODES) {
        g_off[i] = s_prefix + (sh[tid] - v);
        g_cur[i] = 0;
    }
    if (b == 0 && tid == 0) g_off[N_NODES] = N_EDGES;
}

// ---------------------------------------------------------------------------
// CSR step 3: bucket-fill; re-zero g_deg/g_sstate for next replay
// ---------------------------------------------------------------------------
__global__ void k_fill(const int* __restrict__ src, const int* __restrict__ dst)
{
    int e = blockIdx.x * blockDim.x + threadIdx.x;
    if (e < N_EDGES) {
        int d = dst[e];
        int p = atomicAdd(&g_cur[d], 1);
        g_csr[g_off[d] + p] = src[e];
    }
    if (e < N_NODES) g_deg[e] = 0;
    if (e < SCAN_NBLK) g_sstate[e] = 0;
}

// ---------------------------------------------------------------------------
// Fused layer: gather (R10 shape: 16 thr/node, float4, 4-wide unroll)
// + 3-stage FFMA2 MLP (R5/R7 shape) + h write + pooled accumulation.
// Block = 128 threads = 2 groups of 64; 32 nodes/block.
// Gather phase: 8 nodes concurrently (16 threads each), 4 reps.
// ---------------------------------------------------------------------------
#define NB  16
#define NBP 20
#define GROUPS 2
#define NODES_PER_BLOCK (GROUPS * NB)   // 32
#define LAYER_GRID ((N_NODES + NODES_PER_BLOCK - 1) / NODES_PER_BLOCK)  // 1563

__global__ __launch_bounds__(128) void k_layer(const float4* __restrict__ x,
                                               const float* __restrict__ W,
                                               int layer, int use_x)
{
    __shared__ __align__(16) float Ws[DIM * DIM];             // 16 KB
    __shared__ __align__(16) float bufA[GROUPS * DIM * NBP];  // 10 KB
    __shared__ __align__(16) float bufB[GROUPS * DIM * NBP];  // 10 KB
    __shared__ float poolsh[DIM];

    int tid = threadIdx.x;
    int blockBase = blockIdx.x * NODES_PER_BLOCK;

    const float4* hsrc = use_x ? x : reinterpret_cast<const float4*>(g_h);

    // ---- Phase 0: gather straight into bufA ([k][n] layout) ----
    {
        int c = tid & 15;                 // float4 chunk 0..15
#pragma unroll
        for (int rep = 0; rep < 4; rep++) {
            int nb = rep * 8 + (tid >> 4);   // node-in-block 0..31
            int v = blockBase + nb;
            float4 acc = make_float4(0.f, 0.f, 0.f, 0.f);
            if (v < N_NODES) {
                acc = __ldg(&hsrc[v * 16 + c]);
                float4 s1 = make_float4(0.f, 0.f, 0.f, 0.f);
                float4 s2 = make_float4(0.f, 0.f, 0.f, 0.f);
                float4 s3 = make_float4(0.f, 0.f, 0.f, 0.f);
                int j = g_off[v];
                int end = g_off[v + 1];
                for (; j + 4 <= end; j += 4) {
                    int u0 = __ldg(&g_csr[j]);
                    int u1 = __ldg(&g_csr[j + 1]);
                    int u2 = __ldg(&g_csr[j + 2]);
                    int u3 = __ldg(&g_csr[j + 3]);
                    float4 a = __ldg(&hsrc[u0 * 16 + c]);
                    float4 b = __ldg(&hsrc[u1 * 16 + c]);
                    float4 d = __ldg(&hsrc[u2 * 16 + c]);
                    float4 e = __ldg(&hsrc[u3 * 16 + c]);
                    acc.x += a.x; acc.y += a.y; acc.z += a.z; acc.w += a.w;
                    s1.x += b.x;  s1.y += b.y;  s1.z += b.z;  s1.w += b.w;
                    s2.x += d.x;  s2.y += d.y;  s2.z += d.z;  s2.w += d.w;
                    s3.x += e.x;  s3.y += e.y;  s3.z += e.z;  s3.w += e.w;
                }
                for (; j < end; j++) {
                    float4 a = __ldg(&hsrc[__ldg(&g_csr[j]) * 16 + c]);
                    acc.x += a.x; acc.y += a.y; acc.z += a.z; acc.w += a.w;
                }
                acc.x += s1.x + s2.x + s3.x;
                acc.y += s1.y + s2.y + s3.y;
                acc.z += s1.z + s2.z + s3.z;
                acc.w += s1.w + s2.w + s3.w;
            }
            int g = nb >> 4;
            int n = nb & 15;
            float* dp = &bufA[(g * DIM + 4 * c) * NBP + n];
            dp[0 * NBP] = acc.x;
            dp[1 * NBP] = acc.y;
            dp[2 * NBP] = acc.z;
            dp[3 * NBP] = acc.w;
        }
    }
    if (tid < DIM) poolsh[tid] = 0.0f;

    // ---- Phases 1-3: MLP (R5/R7 FFMA2) ----
    int g = tid >> 6;
    int t = tid & 63;
    int base = blockBase + g * NB;

    const float* Wbase = W + (size_t)layer * 3 * DIM * DIM;
    float* inb  = bufA;
    float* outb = bufB;
    float psum = 0.0f;

    for (int s = 0; s < 3; s++) {
        __syncthreads();
        const float4* Wst = reinterpret_cast<const float4*>(Wbase + s * DIM * DIM);
        float4* Wsv = reinterpret_cast<float4*>(Ws);
#pragma unroll
        for (int i = 0; i < DIM * DIM / 4 / 128; i++)
            Wsv[i * 128 + tid] = Wst[i * 128 + tid];
        __syncthreads();

        unsigned long long acc0 = 0ull, acc1 = 0ull, acc2 = 0ull, acc3 = 0ull;
        unsigned long long acc4 = 0ull, acc5 = 0ull, acc6 = 0ull, acc7 = 0ull;
        const ulonglong2* in2 =
            reinterpret_cast<const ulonglong2*>(inb + g * DIM * NBP);

#pragma unroll 4
        for (int k = 0; k < DIM; k++) {
            unsigned int wb = __float_as_uint(Ws[k * DIM + t]);
            unsigned long long wp;
            asm("mov.b64 %0, {%1, %1};" : "=l"(wp) : "r"(wb));
            ulonglong2 q0 = in2[k * 5 + 0];
            ulonglong2 q1 = in2[k * 5 + 1];
            ulonglong2 q2 = in2[k * 5 + 2];
            ulonglong2 q3 = in2[k * 5 + 3];
            asm("fma.rn.f32x2 %0, %1, %2, %0;" : "+l"(acc0) : "l"(q0.x), "l"(wp));
            asm("fma.rn.f32x2 %0, %1, %2, %0;" : "+l"(acc1) : "l"(q0.y), "l"(wp));
            asm("fma.rn.f32x2 %0, %1, %2, %0;" : "+l"(acc2) : "l"(q1.x), "l"(wp));
            asm("fma.rn.f32x2 %0, %1, %2, %0;" : "+l"(acc3) : "l"(q1.y), "l"(wp));
            asm("fma.rn.f32x2 %0, %1, %2, %0;" : "+l"(acc4) : "l"(q2.x), "l"(wp));
            asm("fma.rn.f32x2 %0, %1, %2, %0;" : "+l"(acc5) : "l"(q2.y), "l"(wp));
            asm("fma.rn.f32x2 %0, %1, %2, %0;" : "+l"(acc6) : "l"(q3.x), "l"(wp));
            asm("fma.rn.f32x2 %0, %1, %2, %0;" : "+l"(acc7) : "l"(q3.y), "l"(wp));
        }

        float o[NB];
        {
            float2 a;
            a = *reinterpret_cast<float2*>(&acc0); o[0]  = fmaxf(a.x, 0.f); o[1]  = fmaxf(a.y, 0.f);
            a = *reinterpret_cast<float2*>(&acc1); o[2]  = fmaxf(a.x, 0.f); o[3]  = fmaxf(a.y, 0.f);
            a = *reinterpret_cast<float2*>(&acc2); o[4]  = fmaxf(a.x, 0.f); o[5]  = fmaxf(a.y, 0.f);
            a = *reinterpret_cast<float2*>(&acc3); o[6]  = fmaxf(a.x, 0.f); o[7]  = fmaxf(a.y, 0.f);
            a = *reinterpret_cast<float2*>(&acc4); o[8]  = fmaxf(a.x, 0.f); o[9]  = fmaxf(a.y, 0.f);
            a = *reinterpret_cast<float2*>(&acc5); o[10] = fmaxf(a.x, 0.f); o[11] = fmaxf(a.y, 0.f);
            a = *reinterpret_cast<float2*>(&acc6); o[12] = fmaxf(a.x, 0.f); o[13] = fmaxf(a.y, 0.f);
            a = *reinterpret_cast<float2*>(&acc7); o[14] = fmaxf(a.x, 0.f); o[15] = fmaxf(a.y, 0.f);
        }

        float* ob = outb + (g * DIM + t) * NBP;
        reinterpret_cast<float4*>(ob)[0] = make_float4(o[0],  o[1],  o[2],  o[3]);
        reinterpret_cast<float4*>(ob)[1] = make_float4(o[4],  o[5],  o[6],  o[7]);
        reinterpret_cast<float4*>(ob)[2] = make_float4(o[8],  o[9],  o[10], o[11]);
        reinterpret_cast<float4*>(ob)[3] = make_float4(o[12], o[13], o[14], o[15]);

        if (s == 2) {
            float ps = 0.0f;
#pragma unroll
            for (int n = 0; n < NB; n++) {
                int node = base + n;
                if (node < N_NODES) {
                    g_h[node * DIM + t] = o[n];
                    ps += o[n];
                }
            }
            psum = ps;
        }
        float* tmp = inb; inb = outb; outb = tmp;
    }

    __syncthreads();
    atomicAdd(&poolsh[t], psum);
    __syncthreads();
    if (tid < DIM)
        atomicAdd(&g_pooled[layer * DIM + tid], poolsh[tid]);
}

// ---------------------------------------------------------------------------
// Final: out = sigmoid( sum_l dot(pooled_l / N, Wl_l) ); re-zero g_pooled
// ---------------------------------------------------------------------------
__global__ void k_final(const float* __restrict__ Wl, float* __restrict__ out)
{
    __shared__ float red[128];
    int tid = threadIdx.x;
    float s = 0.0f;
    for (int i = tid; i < N_LAYERS * DIM; i += 128)
        s += g_pooled[i] * Wl[i];
    red[tid] = s;
    __syncthreads();
    for (int i = tid; i < N_LAYERS * DIM; i += 128)
        g_pooled[i] = 0.0f;
    for (int o = 64; o > 0; o >>= 1) {
        if (tid < o) red[tid] += red[tid + o];
        __syncthreads();
    }
    if (tid == 0) {
        float v = red[0] / (float)N_NODES;
        out[0] = 1.0f / (1.0f + expf(-v));
    }
}

// ---------------------------------------------------------------------------
// Launch (k_layer layer0 at idx 3 -> ncu capture target)
// ---------------------------------------------------------------------------
extern "C" void kernel_launch(void* const* d_in, const int* in_sizes, int n_in,
                              void* d_out, int out_size)
{
    const float* x   = (const float*)d_in[0];
    const float* W   = (const float*)d_in[1];
    const float* Wl  = (const float*)d_in[2];
    const int*   src = (const int*)d_in[3];
    const int*   dst = (const int*)d_in[4];
    float*       out = (float*)d_out;

    (void)in_sizes; (void)n_in; (void)out_size;

    k_count<<<(N_EDGES + 255) / 256, 256>>>(dst);          // idx 0
    k_scan<<<SCAN_NBLK, SCAN_BLK>>>();                     // idx 1
    k_fill<<<(N_EDGES + 255) / 256, 256>>>(src, dst);      // idx 2

    for (int l = 0; l < N_LAYERS; l++)
        k_layer<<<LAYER_GRID, 128>>>((const float4*)x, W, l, l == 0 ? 1 : 0);

    k_final<<<1, 128>>>(Wl, out);
}

// round 12
// speedup vs baseline: 2.2586x; 2.1439x over previous
#include <cuda_runtime.h>
#include <cuda_bf16.h>
#include <math.h>
#include <stdint.h>

#define N_NODES 50000
#define N_EDGES 800000
#define DIM     64
#define N_LAYERS 5
#define N_STAGES (N_LAYERS * 3)

#define SCAN_BLK  512
#define SCAN_NBLK ((N_NODES + SCAN_BLK - 1) / SCAN_BLK)   // 98

#define FLAG_AGG (1u << 30)
#define FLAG_INC (2u << 30)
#define VAL_MASK (FLAG_AGG - 1u)

// Scratch (no allocations -> __device__ globals).
// Replay contract: g_hb rewritten from x by k_count_x each replay;
// g_wbh/g_wbl rewritten by k_fill_w; g_deg/g_sstate re-zeroed by k_fill_w;
// g_cur by k_scan; g_pooled by k_final. .bss zero on first run.
__device__ __align__(16) __nv_bfloat16 g_hb[N_NODES * DIM];     // h, bf16
__device__ __align__(16) __nv_bfloat16 g_aggb[N_NODES * DIM];   // agg, bf16
__device__ __align__(16) __nv_bfloat16 g_wbh[N_STAGES * DIM * DIM]; // W hi, pre-swizzled
__device__ __align__(16) __nv_bfloat16 g_wbl[N_STAGES * DIM * DIM]; // W lo, pre-swizzled
__device__ float    g_pooled[N_LAYERS * DIM];
__device__ int      g_deg[N_NODES];
__device__ int      g_cur[N_NODES];
__device__ int      g_off[N_NODES + 1];
__device__ int      g_csr[N_EDGES];
__device__ unsigned g_sstate[SCAN_NBLK];

__device__ __forceinline__ uint32_t pack_bf2(float a, float b)
{
    return (uint32_t)__bfloat16_as_ushort(__float2bfloat16(a))
         | ((uint32_t)__bfloat16_as_ushort(__float2bfloat16(b)) << 16);
}

// ---------------------------------------------------------------------------
// idx0: histogram of dst + convert x -> bf16 h (re-init every replay)
// ---------------------------------------------------------------------------
__global__ void k_count_x(const int* __restrict__ dst, const float2* __restrict__ x2)
{
    int i = blockIdx.x * blockDim.x + threadIdx.x;
    if (i < N_EDGES)
        atomicAdd(&g_deg[dst[i]], 1);
    if (i < N_NODES * DIM / 2) {
        float2 v = __ldg(&x2[i]);
        reinterpret_cast<uint32_t*>(g_hb)[i] = pack_bf2(v.x, v.y);
    }
}

// ---------------------------------------------------------------------------
// idx1: single-pass exclusive scan (decoupled lookback). Zeroes g_cur.
// ---------------------------------------------------------------------------
__global__ void k_scan()
{
    __shared__ int sh[SCAN_BLK];
    __shared__ int s_prefix;
    int tid = threadIdx.x;
    int b   = blockIdx.x;
    int i   = b * SCAN_BLK + tid;
    int v   = (i < N_NODES) ? g_deg[i] : 0;

    sh[tid] = v;
    __syncthreads();
    for (int o = 1; o < SCAN_BLK; o <<= 1) {
        int t = (tid >= o) ? sh[tid - o] : 0;
        __syncthreads();
        sh[tid] += t;
        __syncthreads();
    }
    int total = sh[SCAN_BLK - 1];

    if (tid < 32) {
        int lane = tid;
        if (lane == 0) {
            unsigned pub = (b == 0) ? (FLAG_INC | (unsigned)total)
                                    : (FLAG_AGG | (unsigned)total);
            atomicExch(&g_sstate[b], pub);
        }
        __syncwarp();

        int run = 0;
        if (b > 0) {
            int j = b - 1;
            while (true) {
                int idx = j - lane;
                bool have = (idx >= 0);
                unsigned s = 0;
                if (have) {
                    do { s = atomicAdd(&g_sstate[idx], 0u); } while (s < FLAG_AGG);
                }
                unsigned incmask = __ballot_sync(0xffffffffu, have && (s >= FLAG_INC));
                int firstinc = incmask ? (__ffs(incmask) - 1) : 32;
                unsigned contrib = (have && lane <= firstinc) ? (s & VAL_MASK) : 0u;
                for (int o = 16; o > 0; o >>= 1)
                    contrib += __shfl_down_sync(0xffffffffu, contrib, o);
                contrib = __shfl_sync(0xffffffffu, contrib, 0);
                run += (int)contrib;
                if (incmask) break;
                j -= 32;
            }
            if (lane == 0)
                atomicExch(&g_sstate[b], FLAG_INC | (unsigned)(run + total));
        }
        if (lane == 0) s_prefix = run;
    }
    __syncthreads();

    if (i < N_NODES) {
        g_off[i] = s_prefix + (sh[tid] - v);
        g_cur[i] = 0;
    }
    if (b == 0 && tid == 0) g_off[N_NODES] = N_EDGES;
}

// ---------------------------------------------------------------------------
// idx2: bucket-fill + precompute weight hi/lo split in B[n][k] swizzled
// layout (byte off = n*128 + (((k>>3)^(n&7))<<4) + (k&7)*2 -> element
// off = n*64 + (((k>>3)^(n&7))<<3) + (k&7)), so per-block weight setup in
// the MLP is a raw copy. Re-zeroes g_deg/g_sstate for next replay.
// ---------------------------------------------------------------------------
__global__ void k_fill_w(const int* __restrict__ src, const int* __restrict__ dst,
                         const float* __restrict__ W)
{
    int e = blockIdx.x * blockDim.x + threadIdx.x;
    if (e < N_EDGES) {
        int d = dst[e];
        int p = atomicAdd(&g_cur[d], 1);
        g_csr[g_off[d] + p] = src[e];
    }
    if (e < N_STAGES * DIM * DIM) {
        int stage = e >> 12;
        int idx   = e & 4095;
        int k = idx >> 6, n = idx & 63;
        float w = __ldg(&W[e]);   // W[l][s][k][n] row-major == flat e
        __nv_bfloat16 wh = __float2bfloat16(w);
        float wl = w - __bfloat162float(wh);
        uint32_t off = (uint32_t)n * 64 + ((((uint32_t)k >> 3) ^ (n & 7)) << 3) + (k & 7);
        g_wbh[stage * 4096 + off] = wh;
        g_wbl[stage * 4096 + off] = __float2bfloat16(wl);
    }
    if (e < N_NODES) g_deg[e] = 0;
    if (e < SCAN_NBLK) g_sstate[e] = 0;
}

// ---------------------------------------------------------------------------
// idx3 (first layer): gather on bf16 h. agg[v] = h[v] + sum h[u], fp32
// accumulation (bf16->f32 unpack is shift/mask, no CVT), bf16 output.
// 8 threads/node, 16B (8 bf16) per thread.
// ---------------------------------------------------------------------------
__device__ __forceinline__ void acc_u32(float* a, uint32_t u)
{
    a[0] += __uint_as_float(u << 16);
    a[1] += __uint_as_float(u & 0xffff0000u);
}
__device__ __forceinline__ void acc_u4(float* a, uint4 q)
{
    acc_u32(a + 0, q.x); acc_u32(a + 2, q.y);
    acc_u32(a + 4, q.z); acc_u32(a + 6, q.w);
}

__global__ void k_gather_b()
{
    int idx = blockIdx.x * blockDim.x + threadIdx.x;
    if (idx >= N_NODES * 8) return;
    int v = idx >> 3;
    int c = idx & 7;

    const uint4* hb = reinterpret_cast<const uint4*>(g_hb);

    float a1[8], a2[8];
#pragma unroll
    for (int i = 0; i < 8; i++) { a1[i] = 0.f; a2[i] = 0.f; }

    acc_u4(a1, __ldg(&hb[v * 8 + c]));

    int j = g_off[v];
    int end = g_off[v + 1];
    for (; j + 2 <= end; j += 2) {
        int u0 = __ldg(&g_csr[j]);
        int u1 = __ldg(&g_csr[j + 1]);
        uint4 qa = __ldg(&hb[u0 * 8 + c]);
        uint4 qb = __ldg(&hb[u1 * 8 + c]);
        acc_u4(a1, qa);
        acc_u4(a2, qb);
    }
    if (j < end)
        acc_u4(a1, __ldg(&hb[__ldg(&g_csr[j]) * 8 + c]));

    uint4 outv;
    outv.x = pack_bf2(a1[0] + a2[0], a1[1] + a2[1]);
    outv.y = pack_bf2(a1[2] + a2[2], a1[3] + a2[3]);
    outv.z = pack_bf2(a1[4] + a2[4], a1[5] + a2[5]);
    outv.w = pack_bf2(a1[6] + a2[6], a1[7] + a2[7]);
    reinterpret_cast<uint4*>(g_aggb)[v * 8 + c] = outv;
}

// ---------------------------------------------------------------------------
// HMMA MLP, 2-term (a*wh + a*wl). 256 thr = 8 warps, 128 nodes/CTA.
// A bf16 (no split) in XOR-swizzled smem; weights copied pre-split from
// global. ldmatrix/mma/swizzle patterns identical to the verified R9 kernel.
// ---------------------------------------------------------------------------
#define TILE_M 128
#define MLP_GRID ((N_NODES + TILE_M - 1) / TILE_M)   // 391

struct __align__(16) H2Smem {
    __nv_bfloat16 a[TILE_M * 64];   // 16 KB
    __nv_bfloat16 bh[64 * 64];      //  8 KB
    __nv_bfloat16 bl[64 * 64];      //  8 KB
    float pool[DIM];
};

__device__ __forceinline__ uint32_t smem_u32(const void* p)
{
    uint32_t a;
    asm("{ .reg .u64 t; cvta.to.shared.u64 t, %1; cvt.u32.u64 %0, t; }"
        : "=r"(a) : "l"(p));
    return a;
}
__device__ __forceinline__ void ldsm4(uint32_t* r, uint32_t addr)
{
    asm volatile("ldmatrix.sync.aligned.m8n8.x4.shared.b16 {%0,%1,%2,%3}, [%4];"
                 : "=r"(r[0]), "=r"(r[1]), "=r"(r[2]), "=r"(r[3]) : "r"(addr));
}
__device__ __forceinline__ void ldsm2(uint32_t* r, uint32_t addr)
{
    asm volatile("ldmatrix.sync.aligned.m8n8.x2.shared.b16 {%0,%1}, [%2];"
                 : "=r"(r[0]), "=r"(r[1]) : "r"(addr));
}
__device__ __forceinline__ void mma16816(float* d, const uint32_t* a, const uint32_t* b)
{
    asm volatile("mma.sync.aligned.m16n8k16.row.col.f32.bf16.bf16.f32 "
                 "{%0,%1,%2,%3}, {%4,%5,%6,%7}, {%8,%9}, {%0,%1,%2,%3};"
                 : "+f"(d[0]), "+f"(d[1]), "+f"(d[2]), "+f"(d[3])
                 : "r"(a[0]), "r"(a[1]), "r"(a[2]), "r"(a[3]),
                   "r"(b[0]), "r"(b[1]));
}

__global__ __launch_bounds__(256) void k_mlp_h2(int layer)
{
    __shared__ H2Smem sm;

    int tid  = threadIdx.x;
    int lane = tid & 31;
    int w    = tid >> 5;
    int m0   = w * 16;
    int blockBase = blockIdx.x * TILE_M;

    char* a_c = reinterpret_cast<char*>(sm.a);

    // ---- A load: bf16 agg rows, straight uint4 copy with chunk-XOR swizzle ----
    {
        const uint4* agg4 = reinterpret_cast<const uint4*>(g_aggb);
#pragma unroll
        for (int r = 0; r < 4; r++) {
            int j = tid + 256 * r;
            int row = j >> 3, ch = j & 7;
            int node = blockBase + row;
            uint4 val = make_uint4(0, 0, 0, 0);
            if (node < N_NODES) val = __ldg(&agg4[node * 8 + ch]);
            uint32_t off = (uint32_t)row * 128 + ((uint32_t)(ch ^ (row & 7)) << 4);
            *reinterpret_cast<uint4*>(a_c + off) = val;
        }
    }
    if (tid < DIM) sm.pool[tid] = 0.f;

    uint32_t a_base  = smem_u32(sm.a);
    uint32_t bh_base = smem_u32(sm.bh);
    uint32_t bl_base = smem_u32(sm.bl);
    int r0 = m0 + (lane >> 2);
    int r1 = r0 + 8;

    for (int s = 0; s < 3; s++) {
        // ---- weight copy: pre-split, pre-swizzled -> raw uint4 copy ----
        {
            const uint4* wh4 = reinterpret_cast<const uint4*>(
                g_wbh + (size_t)(layer * 3 + s) * 4096);
            const uint4* wl4 = reinterpret_cast<const uint4*>(
                g_wbl + (size_t)(layer * 3 + s) * 4096);
            uint4* sh = reinterpret_cast<uint4*>(sm.bh);
            uint4* sl = reinterpret_cast<uint4*>(sm.bl);
            sh[tid]       = __ldg(&wh4[tid]);
            sh[tid + 256] = __ldg(&wh4[tid + 256]);
            sl[tid]       = __ldg(&wl4[tid]);
            sl[tid + 256] = __ldg(&wl4[tid + 256]);
        }
        __syncthreads();

        float acc[8][4];
#pragma unroll
        for (int nt = 0; nt < 8; nt++)
#pragma unroll
            for (int q = 0; q < 4; q++) acc[nt][q] = 0.f;

#pragma unroll
        for (int kk = 0; kk < 4; kk++) {
            int arow = m0 + (lane & 15);
            uint32_t achunk = (uint32_t)(kk * 2 + (lane >> 4));
            uint32_t aoff = (uint32_t)arow * 128 + ((achunk ^ (arow & 7)) << 4);
            uint32_t aa[4];
            ldsm4(aa, a_base + aoff);

            int brow_l = lane & 7;
            uint32_t bchunk = (uint32_t)(kk * 2 + ((lane >> 3) & 1));
#pragma unroll
            for (int nt = 0; nt < 8; nt++) {
                int brow = nt * 8 + brow_l;
                uint32_t boff = (uint32_t)brow * 128 + ((bchunk ^ (brow & 7)) << 4);
                uint32_t bh[2], bl[2];
                ldsm2(bh, bh_base + boff);
                ldsm2(bl, bl_base + boff);
                mma16816(acc[nt], aa, bh);
                mma16816(acc[nt], aa, bl);
            }
        }
        __syncthreads();

        if (s < 2) {
            // ---- ReLU + bf16 repack into A for next stage ----
#pragma unroll
            for (int nt = 0; nt < 8; nt++) {
                float v00 = fmaxf(acc[nt][0], 0.f);
                float v01 = fmaxf(acc[nt][1], 0.f);
                float v10 = fmaxf(acc[nt][2], 0.f);
                float v11 = fmaxf(acc[nt][3], 0.f);
                int p = nt * 4 + (lane & 3);
                uint32_t off0 = (uint32_t)r0 * 128 + (((uint32_t)(p >> 2) ^ (r0 & 7)) << 4) + (p & 3) * 4;
                uint32_t off1 = (uint32_t)r1 * 128 + (((uint32_t)(p >> 2) ^ (r1 & 7)) << 4) + (p & 3) * 4;
                *reinterpret_cast<uint32_t*>(a_c + off0) = pack_bf2(v00, v01);
                *reinterpret_cast<uint32_t*>(a_c + off1) = pack_bf2(v10, v11);
            }
            __syncthreads();   // rewrite done before next-stage b copy races readers
        } else {
            // ---- final: h (bf16) write + pooled sum ----
            int node0 = blockBase + r0;
            int node1 = blockBase + r1;
            uint32_t* hb32 = reinterpret_cast<uint32_t*>(g_hb);
#pragma unroll
            for (int nt = 0; nt < 8; nt++) {
                float v00 = fmaxf(acc[nt][0], 0.f);
                float v01 = fmaxf(acc[nt][1], 0.f);
                float v10 = fmaxf(acc[nt][2], 0.f);
                float v11 = fmaxf(acc[nt][3], 0.f);
                int p = nt * 4 + (lane & 3);   // bf16-pair index = col/2
                if (node0 < N_NODES) hb32[node0 * 32 + p] = pack_bf2(v00, v01);
                if (node1 < N_NODES) hb32[node1 * 32 + p] = pack_bf2(v10, v11);
                // pool: invalid rows contribute exactly 0 (zeroed A -> zero acc)
                float s0 = v00 + v10, s1 = v01 + v11;
                s0 += __shfl_xor_sync(0xffffffffu, s0, 16);
                s0 += __shfl_xor_sync(0xffffffffu, s0, 8);
                s0 += __shfl_xor_sync(0xffffffffu, s0, 4);
                s1 += __shfl_xor_sync(0xffffffffu, s1, 16);
                s1 += __shfl_xor_sync(0xffffffffu, s1, 8);
                s1 += __shfl_xor_sync(0xffffffffu, s1, 4);
                if ((lane >> 2) == 0) {
                    int c0 = nt * 8 + (lane & 3) * 2;
                    atomicAdd(&sm.pool[c0],     s0);
                    atomicAdd(&sm.pool[c0 + 1], s1);
                }
            }
            __syncthreads();
            if (tid < DIM)
                atomicAdd(&g_pooled[layer * DIM + tid], sm.pool[tid]);
        }
    }
}

// ---------------------------------------------------------------------------
// Final: out = sigmoid( sum_l dot(pooled_l / N, Wl_l) ); re-zero g_pooled
// ---------------------------------------------------------------------------
__global__ void k_final(const float* __restrict__ Wl, float* __restrict__ out)
{
    __shared__ float red[128];
    int tid = threadIdx.x;
    float s = 0.0f;
    for (int i = tid; i < N_LAYERS * DIM; i += 128)
        s += g_pooled[i] * Wl[i];
    red[tid] = s;
    __syncthreads();
    for (int i = tid; i < N_LAYERS * DIM; i += 128)
        g_pooled[i] = 0.0f;
    for (int o = 64; o > 0; o >>= 1) {
        if (tid < o) red[tid] += red[tid + o];
        __syncthreads();
    }
    if (tid == 0) {
        float v = red[0] / (float)N_NODES;
        out[0] = 1.0f / (1.0f + expf(-v));
    }
}

// ---------------------------------------------------------------------------
// Launch (first k_gather_b at idx 3 -> ncu capture target)
// ---------------------------------------------------------------------------
extern "C" void kernel_launch(void* const* d_in, const int* in_sizes, int n_in,
                              void* d_out, int out_size)
{
    const float* x   = (const float*)d_in[0];
    const float* W   = (const float*)d_in[1];
    const float* Wl  = (const float*)d_in[2];
    const int*   src = (const int*)d_in[3];
    const int*   dst = (const int*)d_in[4];
    float*       out = (float*)d_out;

    (void)in_sizes; (void)n_in; (void)out_size;

    k_count_x<<<(N_NODES * DIM / 2 + 255) / 256, 256>>>(dst, (const float2*)x); // idx0
    k_scan<<<SCAN_NBLK, SCAN_BLK>>>();                                          // idx1
    k_fill_w<<<(N_EDGES + 255) / 256, 256>>>(src, dst, W);                      // idx2

    int gather_blocks = (N_NODES * 8 + 255) / 256;

    for (int l = 0; l < N_LAYERS; l++) {
        k_gather_b<<<gather_blocks, 256>>>();     // idx3 on first layer
        k_mlp_h2<<<MLP_GRID, 256>>>(l);
    }
    k_final<<<1, 128>>>(Wl, out);
}

// round 13
// speedup vs baseline: 2.2676x; 1.0040x over previous
#include <cuda_runtime.h>
#include <cuda_bf16.h>
#include <math.h>
#include <stdint.h>

#define N_NODES 50000
#define N_EDGES 800000
#define DIM     64
#define N_LAYERS 5
#define N_STAGES (N_LAYERS * 3)

#define SCAN_BLK  512
#define SCAN_NBLK ((N_NODES + SCAN_BLK - 1) / SCAN_BLK)   // 98

#define FLAG_AGG (1u << 30)
#define FLAG_INC (2u << 30)
#define VAL_MASK (FLAG_AGG - 1u)

// Scratch (no allocations -> __device__ globals).
// Replay contract: g_hb rewritten by k_count_x; g_wbh/g_wbl by k_fill_w;
// g_deg/g_sstate re-zeroed by k_fill_w; g_cur by k_scan; g_pooled by k_final.
__device__ __align__(16) __nv_bfloat16 g_hb[N_NODES * DIM];
__device__ __align__(16) __nv_bfloat16 g_aggb[N_NODES * DIM];
__device__ __align__(16) __nv_bfloat16 g_wbh[N_STAGES * DIM * DIM];
__device__ __align__(16) __nv_bfloat16 g_wbl[N_STAGES * DIM * DIM];
__device__ float    g_pooled[N_LAYERS * DIM];
__device__ int      g_deg[N_NODES];
__device__ int      g_cur[N_NODES];
__device__ int      g_off[N_NODES + 1];
__device__ int      g_csr[N_EDGES];
__device__ unsigned g_sstate[SCAN_NBLK];

__device__ __forceinline__ uint32_t pack_bf2(float a, float b)
{
    return (uint32_t)__bfloat16_as_ushort(__float2bfloat16(a))
         | ((uint32_t)__bfloat16_as_ushort(__float2bfloat16(b)) << 16);
}

// ---------------------------------------------------------------------------
// idx0: histogram of dst + convert x -> bf16 h
// ---------------------------------------------------------------------------
__global__ void k_count_x(const int* __restrict__ dst, const float2* __restrict__ x2)
{
    int i = blockIdx.x * blockDim.x + threadIdx.x;
    if (i < N_EDGES)
        atomicAdd(&g_deg[dst[i]], 1);
    if (i < N_NODES * DIM / 2) {
        float2 v = __ldg(&x2[i]);
        reinterpret_cast<uint32_t*>(g_hb)[i] = pack_bf2(v.x, v.y);
    }
}

// ---------------------------------------------------------------------------
// idx1: single-pass exclusive scan (decoupled lookback). Zeroes g_cur.
// ---------------------------------------------------------------------------
__global__ void k_scan()
{
    __shared__ int sh[SCAN_BLK];
    __shared__ int s_prefix;
    int tid = threadIdx.x;
    int b   = blockIdx.x;
    int i   = b * SCAN_BLK + tid;
    int v   = (i < N_NODES) ? g_deg[i] : 0;

    sh[tid] = v;
    __syncthreads();
    for (int o = 1; o < SCAN_BLK; o <<= 1) {
        int t = (tid >= o) ? sh[tid - o] : 0;
        __syncthreads();
        sh[tid] += t;
        __syncthreads();
    }
    int total = sh[SCAN_BLK - 1];

    if (tid < 32) {
        int lane = tid;
        if (lane == 0) {
            unsigned pub = (b == 0) ? (FLAG_INC | (unsigned)total)
                                    : (FLAG_AGG | (unsigned)total);
            atomicExch(&g_sstate[b], pub);
        }
        __syncwarp();

        int run = 0;
        if (b > 0) {
            int j = b - 1;
            while (true) {
                int idx = j - lane;
                bool have = (idx >= 0);
                unsigned s = 0;
                if (have) {
                    do { s = atomicAdd(&g_sstate[idx], 0u); } while (s < FLAG_AGG);
                }
                unsigned incmask = __ballot_sync(0xffffffffu, have && (s >= FLAG_INC));
                int firstinc = incmask ? (__ffs(incmask) - 1) : 32;
                unsigned contrib = (have && lane <= firstinc) ? (s & VAL_MASK) : 0u;
                for (int o = 16; o > 0; o >>= 1)
                    contrib += __shfl_down_sync(0xffffffffu, contrib, o);
                contrib = __shfl_sync(0xffffffffu, contrib, 0);
                run += (int)contrib;
                if (incmask) break;
                j -= 32;
            }
            if (lane == 0)
                atomicExch(&g_sstate[b], FLAG_INC | (unsigned)(run + total));
        }
        if (lane == 0) s_prefix = run;
    }
    __syncthreads();

    if (i < N_NODES) {
        g_off[i] = s_prefix + (sh[tid] - v);
        g_cur[i] = 0;
    }
    if (b == 0 && tid == 0) g_off[N_NODES] = N_EDGES;
}

// ---------------------------------------------------------------------------
// idx2: bucket-fill + precompute weight hi/lo split (B[n][k] swizzled).
// Re-zeroes g_deg/g_sstate for next replay.
// ---------------------------------------------------------------------------
__global__ void k_fill_w(const int* __restrict__ src, const int* __restrict__ dst,
                         const float* __restrict__ W)
{
    int e = blockIdx.x * blockDim.x + threadIdx.x;
    if (e < N_EDGES) {
        int d = dst[e];
        int p = atomicAdd(&g_cur[d], 1);
        g_csr[g_off[d] + p] = src[e];
    }
    if (e < N_STAGES * DIM * DIM) {
        int stage = e >> 12;
        int idx   = e & 4095;
        int k = idx >> 6, n = idx & 63;
        float w = __ldg(&W[e]);
        __nv_bfloat16 wh = __float2bfloat16(w);
        float wl = w - __bfloat162float(wh);
        uint32_t off = (uint32_t)n * 64 + ((((uint32_t)k >> 3) ^ (n & 7)) << 3) + (k & 7);
        g_wbh[stage * 4096 + off] = wh;
        g_wbl[stage * 4096 + off] = __float2bfloat16(wl);
    }
    if (e < N_NODES) g_deg[e] = 0;
    if (e < SCAN_NBLK) g_sstate[e] = 0;
}

// ---------------------------------------------------------------------------
// Gather v3: bf16 HADD2 accumulation, 4 independent accumulators (4-way ILP).
// 8 threads/node, 16B (8 bf16) per thread. Per-chain length ~deg/4 adds.
// ---------------------------------------------------------------------------
__device__ __forceinline__ uint32_t hadd2u(uint32_t a, uint32_t b)
{
    __nv_bfloat162 r = __hadd2(*reinterpret_cast<__nv_bfloat162*>(&a),
                               *reinterpret_cast<__nv_bfloat162*>(&b));
    return *reinterpret_cast<uint32_t*>(&r);
}
__device__ __forceinline__ uint4 hadd2q(uint4 a, uint4 b)
{
    return make_uint4(hadd2u(a.x, b.x), hadd2u(a.y, b.y),
                      hadd2u(a.z, b.z), hadd2u(a.w, b.w));
}

__global__ void k_gather_b()
{
    int idx = blockIdx.x * blockDim.x + threadIdx.x;
    if (idx >= N_NODES * 8) return;
    int v = idx >> 3;
    int c = idx & 7;

    const uint4* hb = reinterpret_cast<const uint4*>(g_hb);

    uint4 A0 = __ldg(&hb[v * 8 + c]);   // self term
    uint4 A1 = make_uint4(0, 0, 0, 0);  // bf16 +0 is exact identity
    uint4 A2 = make_uint4(0, 0, 0, 0);
    uint4 A3 = make_uint4(0, 0, 0, 0);

    int j = g_off[v];
    int end = g_off[v + 1];

    for (; j + 4 <= end; j += 4) {
        int u0 = __ldg(&g_csr[j]);
        int u1 = __ldg(&g_csr[j + 1]);
        int u2 = __ldg(&g_csr[j + 2]);
        int u3 = __ldg(&g_csr[j + 3]);
        uint4 q0 = __ldg(&hb[u0 * 8 + c]);
        uint4 q1 = __ldg(&hb[u1 * 8 + c]);
        uint4 q2 = __ldg(&hb[u2 * 8 + c]);
        uint4 q3 = __ldg(&hb[u3 * 8 + c]);
        A0 = hadd2q(A0, q0);
        A1 = hadd2q(A1, q1);
        A2 = hadd2q(A2, q2);
        A3 = hadd2q(A3, q3);
    }
    for (; j < end; j++)
        A0 = hadd2q(A0, __ldg(&hb[__ldg(&g_csr[j]) * 8 + c]));

    A0 = hadd2q(hadd2q(A0, A1), hadd2q(A2, A3));
    reinterpret_cast<uint4*>(g_aggb)[v * 8 + c] = A0;
}

// ---------------------------------------------------------------------------
// HMMA MLP, 2-term (unchanged from R12 — measured 11.6us/layer, rel_err 0.0)
// ---------------------------------------------------------------------------
#define TILE_M 128
#define MLP_GRID ((N_NODES + TILE_M - 1) / TILE_M)   // 391

struct __align__(16) H2Smem {
    __nv_bfloat16 a[TILE_M * 64];
    __nv_bfloat16 bh[64 * 64];
    __nv_bfloat16 bl[64 * 64];
    float pool[DIM];
};

__device__ __forceinline__ uint32_t smem_u32(const void* p)
{
    uint32_t a;
    asm("{ .reg .u64 t; cvta.to.shared.u64 t, %1; cvt.u32.u64 %0, t; }"
        : "=r"(a) : "l"(p));
    return a;
}
__device__ __forceinline__ void ldsm4(uint32_t* r, uint32_t addr)
{
    asm volatile("ldmatrix.sync.aligned.m8n8.x4.shared.b16 {%0,%1,%2,%3}, [%4];"
                 : "=r"(r[0]), "=r"(r[1]), "=r"(r[2]), "=r"(r[3]) : "r"(addr));
}
__device__ __forceinline__ void ldsm2(uint32_t* r, uint32_t addr)
{
    asm volatile("ldmatrix.sync.aligned.m8n8.x2.shared.b16 {%0,%1}, [%2];"
                 : "=r"(r[0]), "=r"(r[1]) : "r"(addr));
}
__device__ __forceinline__ void mma16816(float* d, const uint32_t* a, const uint32_t* b)
{
    asm volatile("mma.sync.aligned.m16n8k16.row.col.f32.bf16.bf16.f32 "
                 "{%0,%1,%2,%3}, {%4,%5,%6,%7}, {%8,%9}, {%0,%1,%2,%3};"
                 : "+f"(d[0]), "+f"(d[1]), "+f"(d[2]), "+f"(d[3])
                 : "r"(a[0]), "r"(a[1]), "r"(a[2]), "r"(a[3]),
                   "r"(b[0]), "r"(b[1]));
}

__global__ __launch_bounds__(256) void k_mlp_h2(int layer)
{
    __shared__ H2Smem sm;

    int tid  = threadIdx.x;
    int lane = tid & 31;
    int w    = tid >> 5;
    int m0   = w * 16;
    int blockBase = blockIdx.x * TILE_M;

    char* a_c = reinterpret_cast<char*>(sm.a);

    {
        const uint4* agg4 = reinterpret_cast<const uint4*>(g_aggb);
#pragma unroll
        for (int r = 0; r < 4; r++) {
            int j = tid + 256 * r;
            int row = j >> 3, ch = j & 7;
            int node = blockBase + row;
            uint4 val = make_uint4(0, 0, 0, 0);
            if (node < N_NODES) val = __ldg(&agg4[node * 8 + ch]);
            uint32_t off = (uint32_t)row * 128 + ((uint32_t)(ch ^ (row & 7)) << 4);
            *reinterpret_cast<uint4*>(a_c + off) = val;
        }
    }
    if (tid < DIM) sm.pool[tid] = 0.f;

    uint32_t a_base  = smem_u32(sm.a);
    uint32_t bh_base = smem_u32(sm.bh);
    uint32_t bl_base = smem_u32(sm.bl);
    int r0 = m0 + (lane >> 2);
    int r1 = r0 + 8;

    for (int s = 0; s < 3; s++) {
        {
            const uint4* wh4 = reinterpret_cast<const uint4*>(
                g_wbh + (size_t)(layer * 3 + s) * 4096);
            const uint4* wl4 = reinterpret_cast<const uint4*>(
                g_wbl + (size_t)(layer * 3 + s) * 4096);
            uint4* sh = reinterpret_cast<uint4*>(sm.bh);
            uint4* sl = reinterpret_cast<uint4*>(sm.bl);
            sh[tid]       = __ldg(&wh4[tid]);
            sh[tid + 256] = __ldg(&wh4[tid + 256]);
            sl[tid]       = __ldg(&wl4[tid]);
            sl[tid + 256] = __ldg(&wl4[tid + 256]);
        }
        __syncthreads();

        float acc[8][4];
#pragma unroll
        for (int nt = 0; nt < 8; nt++)
#pragma unroll
            for (int q = 0; q < 4; q++) acc[nt][q] = 0.f;

#pragma unroll
        for (int kk = 0; kk < 4; kk++) {
            int arow = m0 + (lane & 15);
            uint32_t achunk = (uint32_t)(kk * 2 + (lane >> 4));
            uint32_t aoff = (uint32_t)arow * 128 + ((achunk ^ (arow & 7)) << 4);
            uint32_t aa[4];
            ldsm4(aa, a_base + aoff);

            int brow_l = lane & 7;
            uint32_t bchunk = (uint32_t)(kk * 2 + ((lane >> 3) & 1));
#pragma unroll
            for (int nt = 0; nt < 8; nt++) {
                int brow = nt * 8 + brow_l;
                uint32_t boff = (uint32_t)brow * 128 + ((bchunk ^ (brow & 7)) << 4);
                uint32_t bh[2], bl[2];
                ldsm2(bh, bh_base + boff);
                ldsm2(bl, bl_base + boff);
                mma16816(acc[nt], aa, bh);
                mma16816(acc[nt], aa, bl);
            }
        }
        __syncthreads();

        if (s < 2) {
#pragma unroll
            for (int nt = 0; nt < 8; nt++) {
                float v00 = fmaxf(acc[nt][0], 0.f);
                float v01 = fmaxf(acc[nt][1], 0.f);
                float v10 = fmaxf(acc[nt][2], 0.f);
                float v11 = fmaxf(acc[nt][3], 0.f);
                int p = nt * 4 + (lane & 3);
                uint32_t off0 = (uint32_t)r0 * 128 + (((uint32_t)(p >> 2) ^ (r0 & 7)) << 4) + (p & 3) * 4;
                uint32_t off1 = (uint32_t)r1 * 128 + (((uint32_t)(p >> 2) ^ (r1 & 7)) << 4) + (p & 3) * 4;
                *reinterpret_cast<uint32_t*>(a_c + off0) = pack_bf2(v00, v01);
                *reinterpret_cast<uint32_t*>(a_c + off1) = pack_bf2(v10, v11);
            }
            __syncthreads();
        } else {
            int node0 = blockBase + r0;
            int node1 = blockBase + r1;
            uint32_t* hb32 = reinterpret_cast<uint32_t*>(g_hb);
#pragma unroll
            for (int nt = 0; nt < 8; nt++) {
                float v00 = fmaxf(acc[nt][0], 0.f);
                float v01 = fmaxf(acc[nt][1], 0.f);
                float v10 = fmaxf(acc[nt][2], 0.f);
                float v11 = fmaxf(acc[nt][3], 0.f);
                int p = nt * 4 + (lane & 3);
                if (node0 < N_NODES) hb32[node0 * 32 + p] = pack_bf2(v00, v01);
                if (node1 < N_NODES) hb32[node1 * 32 + p] = pack_bf2(v10, v11);
                float s0 = v00 + v10, s1 = v01 + v11;
                s0 += __shfl_xor_sync(0xffffffffu, s0, 16);
                s0 += __shfl_xor_sync(0xffffffffu, s0, 8);
                s0 += __shfl_xor_sync(0xffffffffu, s0, 4);
                s1 += __shfl_xor_sync(0xffffffffu, s1, 16);
                s1 += __shfl_xor_sync(0xffffffffu, s1, 8);
                s1 += __shfl_xor_sync(0xffffffffu, s1, 4);
                if ((lane >> 2) == 0) {
                    int c0 = nt * 8 + (lane & 3) * 2;
                    atomicAdd(&sm.pool[c0],     s0);
                    atomicAdd(&sm.pool[c0 + 1], s1);
                }
            }
            __syncthreads();
            if (tid < DIM)
                atomicAdd(&g_pooled[layer * DIM + tid], sm.pool[tid]);
        }
    }
}

// ---------------------------------------------------------------------------
// Final: out = sigmoid( sum_l dot(pooled_l / N, Wl_l) ); re-zero g_pooled
// ---------------------------------------------------------------------------
__global__ void k_final(const float* __restrict__ Wl, float* __restrict__ out)
{
    __shared__ float red[128];
    int tid = threadIdx.x;
    float s = 0.0f;
    for (int i = tid; i < N_LAYERS * DIM; i += 128)
        s += g_pooled[i] * Wl[i];
    red[tid] = s;
    __syncthreads();
    for (int i = tid; i < N_LAYERS * DIM; i += 128)
        g_pooled[i] = 0.0f;
    for (int o = 64; o > 0; o >>= 1) {
        if (tid < o) red[tid] += red[tid + o];
        __syncthreads();
    }
    if (tid == 0) {
        float v = red[0] / (float)N_NODES;
        out[0] = 1.0f / (1.0f + expf(-v));
    }
}

// ---------------------------------------------------------------------------
// Launch (first k_gather_b at idx 3 -> ncu capture target)
// ---------------------------------------------------------------------------
extern "C" void kernel_launch(void* const* d_in, const int* in_sizes, int n_in,
                              void* d_out, int out_size)
{
    const float* x   = (const float*)d_in[0];
    const float* W   = (const float*)d_in[1];
    const float* Wl  = (const float*)d_in[2];
    const int*   src = (const int*)d_in[3];
    const int*   dst = (const int*)d_in[4];
    float*       out = (float*)d_out;

    (void)in_sizes; (void)n_in; (void)out_size;

    k_count_x<<<(N_NODES * DIM / 2 + 255) / 256, 256>>>(dst, (const float2*)x); // idx0
    k_scan<<<SCAN_NBLK, SCAN_BLK>>>();                                          // idx1
    k_fill_w<<<(N_EDGES + 255) / 256, 256>>>(src, dst, W);                      // idx2

    int gather_blocks = (N_NODES * 8 + 255) / 256;

    for (int l = 0; l < N_LAYERS; l++) {
        k_gather_b<<<gather_blocks, 256>>>();     // idx3 on first layer
        k_mlp_h2<<<MLP_GRID, 256>>>(l);
    }
    k_final<<<1, 128>>>(Wl, out);
}